// round 4
// baseline (speedup 1.0000x reference)
#include <cuda_runtime.h>

typedef unsigned long long ull;
#define DEVFN __device__ __forceinline__

#define TT 32
#define BB 2048
#define DD 64
#define MT 16
#define NTH 256
#define NCTA (BB / MT)

// smem layout (float offsets)
#define OFF_W0T 0                      // [64][256]  W0T[d][w]
#define OFF_W2T (OFF_W0T + 64*256)     // [256][64]  W2T[u][d]
#define OFF_B0  (OFF_W2T + 256*64)
#define OFF_B1  (OFF_B0 + 256)
#define OFF_B2  (OFF_B1 + 256)
#define OFF_TS  (OFF_B2 + 64)
#define OFF_Y   (OFF_TS + 32)          // [64][16]
#define OFF_YT  (OFF_Y + 64*16)        // [64][16]
#define OFF_K   (OFF_YT + 64*16)       // 6 x [64][16]
#define OFF_HD  (OFF_K + 6*64*16)      // [256][36] duplicated activations (h0 then h1)
#define SMEM_FLOATS (OFF_HD + 256*36)  // 50784
#define SMEM_BYTES (SMEM_FLOATS * 4)   // 203136

__device__ float g_W1T[(256 + 32) * 256];   // [k][w], w contiguous

__constant__ float c_A[30] = {
    0.f, 0.f, 0.f, 0.f, 0.f,
    0.2f, 0.f, 0.f, 0.f, 0.f,
    (float)(3.0/40.0), (float)(9.0/40.0), 0.f, 0.f, 0.f,
    (float)(44.0/45.0), (float)(-56.0/15.0), (float)(32.0/9.0), 0.f, 0.f,
    (float)(19372.0/6561.0), (float)(-25360.0/2187.0), (float)(64448.0/6561.0), (float)(-212.0/729.0), 0.f,
    (float)(9017.0/3168.0), (float)(-355.0/33.0), (float)(46732.0/5247.0), (float)(49.0/176.0), (float)(-5103.0/18656.0)
};
__constant__ float c_C6[6] = {0.f, 0.2f, 0.3f, 0.8f, (float)(8.0/9.0), 1.f};
__constant__ float c_B6[6] = {(float)(35.0/384.0), 0.f, (float)(500.0/1113.0),
                              (float)(125.0/192.0), (float)(-2187.0/6784.0), (float)(11.0/84.0)};

DEVFN ull dup2(float x) {
    ull r; unsigned xi = __float_as_uint(x);
    asm("mov.b64 %0, {%1, %1};" : "=l"(r) : "r"(xi));
    return r;
}
DEVFN void fma2(ull& d, ull a, ull b) {
    asm("fma.rn.f32x2 %0, %1, %2, %0;" : "+l"(d) : "l"(a), "l"(b));
}
DEVFN void unpk(ull v, float& lo, float& hi) {
    unsigned a, b;
    asm("mov.b64 {%0, %1}, %2;" : "=r"(a), "=r"(b) : "l"(v));
    lo = __uint_as_float(a); hi = __uint_as_float(b);
}
DEVFN float fast_tanh(float x) {
    float ax = fabsf(x);
    float e  = __expf(-2.0f * ax);
    float r  = __fdividef(1.0f - e, 1.0f + e);
    return copysignf(r, x);
}

// row-pair step (GEMM0): acc[p] = rows (2p,2p+1) of one output column
DEVFN void gstepA(ull (&acc)[8], float bval, const float* pa) {
    ull bb = dup2(bval);
    ulonglong2 a0 = *reinterpret_cast<const ulonglong2*>(pa);
    ulonglong2 a1 = *reinterpret_cast<const ulonglong2*>(pa + 4);
    ulonglong2 a2 = *reinterpret_cast<const ulonglong2*>(pa + 8);
    ulonglong2 a3 = *reinterpret_cast<const ulonglong2*>(pa + 12);
    fma2(acc[0], a0.x, bb); fma2(acc[1], a0.y, bb);
    fma2(acc[2], a1.x, bb); fma2(acc[3], a1.y, bb);
    fma2(acc[4], a2.x, bb); fma2(acc[5], a2.y, bb);
    fma2(acc[6], a3.x, bb); fma2(acc[7], a3.y, bb);
}

// col-pair step (GEMM1): acc[j] = (col c, c+1) for row 8q+j; a = dup'd row values
DEVFN void gstepB(ull (&acc)[8], ull bpair, const float* pa) {
    ulonglong2 a0 = *reinterpret_cast<const ulonglong2*>(pa);
    ulonglong2 a1 = *reinterpret_cast<const ulonglong2*>(pa + 4);
    ulonglong2 a2 = *reinterpret_cast<const ulonglong2*>(pa + 8);
    ulonglong2 a3 = *reinterpret_cast<const ulonglong2*>(pa + 12);
    fma2(acc[0], a0.x, bpair); fma2(acc[1], a0.y, bpair);
    fma2(acc[2], a1.x, bpair); fma2(acc[3], a1.y, bpair);
    fma2(acc[4], a2.x, bpair); fma2(acc[5], a2.y, bpair);
    fma2(acc[6], a3.x, bpair); fma2(acc[7], a3.y, bpair);
}

// kout = (tanh(tanh(aIn@W0T + b0)@W1T + b1)@W2T + b2) * exp(tstage)
DEVFN void vf_eval(float* sm, float tstage, const float* aIn, float* kout, int tid) {
    float et = expf(tstage);
    float* hd = sm + OFF_HD;

    // ---- GEMM0: [16,64] x W0T -> tanh -> hd (dup'd, h0 phase) ----
    {
        ull acc[8];
#pragma unroll
        for (int p = 0; p < 8; ++p) acc[p] = 0ull;
        const float* pb = sm + OFF_W0T + tid;
#pragma unroll 4
        for (int k = 0; k < 64; ++k)
            gstepA(acc, pb[k * 256], aIn + k * 16);
        float bj = sm[OFF_B0 + tid];
        float* hp = hd + tid * 36;
#pragma unroll
        for (int p = 0; p < 8; ++p) {
            float v0, v1; unpk(acc[p], v0, v1);
            ulonglong2 w;
            w.x = dup2(fast_tanh(v0 + bj));
            w.y = dup2(fast_tanh(v1 + bj));
            *reinterpret_cast<ulonglong2*>(hp + 4 * p) = w;  // rows 2p,2p+1 dup'd
        }
    }
    __syncthreads();

    // ---- GEMM1: [16,256] x W1T (L2-streamed, col-pairs) -> tanh -> hd (h1 phase) ----
    {
        int cp = tid & 127, q = tid >> 7;   // col pair c=2cp, rows 8q..8q+7
        int c = 2 * cp;
        ull acc[8];
#pragma unroll
        for (int j = 0; j < 8; ++j) acc[j] = 0ull;
        const float* pb = g_W1T + c;
        const float* pa = hd + 16 * q;
        ull bufA[16], bufB[16];
#pragma unroll
        for (int kk = 0; kk < 16; ++kk)
            bufA[kk] = *reinterpret_cast<const ull*>(pb + kk * 256);
        pb += 16 * 256;
#pragma unroll 1
        for (int kc = 0; kc < 256; kc += 32) {
#pragma unroll
            for (int kk = 0; kk < 16; ++kk)
                bufB[kk] = *reinterpret_cast<const ull*>(pb + kk * 256);
            pb += 16 * 256;
#pragma unroll
            for (int kk = 0; kk < 16; ++kk)
                gstepB(acc, bufA[kk], pa + (kc + kk) * 36);
#pragma unroll
            for (int kk = 0; kk < 16; ++kk)
                bufA[kk] = *reinterpret_cast<const ull*>(pb + kk * 256);
            pb += 16 * 256;
#pragma unroll
            for (int kk = 0; kk < 16; ++kk)
                gstepB(acc, bufB[kk], pa + (kc + 16 + kk) * 36);
        }
        float b1a = sm[OFF_B1 + c], b1b = sm[OFF_B1 + c + 1];
        float t0[8], t1[8];
#pragma unroll
        for (int j = 0; j < 8; ++j) {
            float v0, v1; unpk(acc[j], v0, v1);
            t0[j] = fast_tanh(v0 + b1a);
            t1[j] = fast_tanh(v1 + b1b);
        }
        __syncthreads();   // all reads of h0-phase hd complete before h1 overwrite
        float* hp0 = hd + c * 36 + 16 * q;
        float* hp1 = hd + (c + 1) * 36 + 16 * q;
#pragma unroll
        for (int jj = 0; jj < 4; ++jj) {
            ulonglong2 w0, w1;
            w0.x = dup2(t0[2 * jj]); w0.y = dup2(t0[2 * jj + 1]);
            w1.x = dup2(t1[2 * jj]); w1.y = dup2(t1[2 * jj + 1]);
            *reinterpret_cast<ulonglong2*>(hp0 + 4 * jj) = w0;
            *reinterpret_cast<ulonglong2*>(hp1 + 4 * jj) = w1;
        }
    }
    __syncthreads();

    // ---- GEMM2: [16,256] x W2T (smem, col-pairs) -> kout ----
    {
        int dp = tid & 31, q2 = tid >> 5;   // cols d=2dp,d+1; rows 2q2,2q2+1
        int d = 2 * dp;
        ull acc0 = 0ull, acc1 = 0ull;
        const float* pb = sm + OFF_W2T + d;
        const float* pa = hd + 4 * q2;
#pragma unroll 8
        for (int u = 0; u < 256; ++u) {
            ull bb = *reinterpret_cast<const ull*>(pb + u * 64);
            ulonglong2 av = *reinterpret_cast<const ulonglong2*>(pa + u * 36);
            fma2(acc0, av.x, bb);   // row 2q2
            fma2(acc1, av.y, bb);   // row 2q2+1
        }
        float ba = sm[OFF_B2 + d], bb2 = sm[OFF_B2 + d + 1];
        float v00, v01, v10, v11;
        unpk(acc0, v00, v01);
        unpk(acc1, v10, v11);
        kout[d * 16 + 2 * q2]           = (v00 + ba)  * et;
        kout[d * 16 + 2 * q2 + 1]       = (v10 + ba)  * et;
        kout[(d + 1) * 16 + 2 * q2]     = (v01 + bb2) * et;
        kout[(d + 1) * 16 + 2 * q2 + 1] = (v11 + bb2) * et;
    }
    __syncthreads();
}

__global__ void __launch_bounds__(NTH, 1)
prep_kernel(const float* __restrict__ W1, const float* __restrict__ y0,
            float* __restrict__ out) {
    int stride = gridDim.x * blockDim.x;
    int t0 = blockIdx.x * blockDim.x + threadIdx.x;
    for (int idx = t0; idx < 256 * 256; idx += stride) {
        int r = idx >> 8, c = idx & 255;
        g_W1T[c * 256 + r] = W1[idx];          // [k=c][w=r] = W1[w][k]
    }
    for (int idx = t0; idx < 32 * 256; idx += stride)
        g_W1T[65536 + idx] = 0.f;              // prefetch-overrun pad
    for (int idx = t0; idx < BB * DD; idx += stride)
        out[idx] = y0[idx];                    // out slice 0 = y0
}

__global__ void __launch_bounds__(NTH, 1)
ode_kernel(const float* __restrict__ ts, const float* __restrict__ y0,
           const float* __restrict__ W0, const float* __restrict__ b0,
           const float* __restrict__ b1,
           const float* __restrict__ W2, const float* __restrict__ b2,
           float* __restrict__ out) {
    extern __shared__ float sm[];
    int tid = threadIdx.x;
    int r0 = blockIdx.x * MT;

    for (int idx = tid; idx < 64 * 256; idx += NTH) {
        int w = idx >> 6, d = idx & 63;
        sm[OFF_W0T + d * 256 + w] = W0[idx];   // W0T[d][w]
    }
    for (int idx = tid; idx < 64 * 256; idx += NTH) {
        int d = idx >> 8, u = idx & 255;
        sm[OFF_W2T + u * 64 + d] = W2[idx];    // W2T[u][d]
    }
    if (tid < 256) { sm[OFF_B0 + tid] = b0[tid]; sm[OFF_B1 + tid] = b1[tid]; }
    if (tid < 64)  sm[OFF_B2 + tid] = b2[tid];
    if (tid < 32)  sm[OFF_TS + tid] = ts[tid];
    for (int i = tid; i < MT * DD; i += NTH) {
        int d = i >> 4, m = i & 15;
        sm[OFF_Y + d * 16 + m] = y0[(r0 + m) * DD + d];
    }
    __syncthreads();

    float* sY  = sm + OFF_Y;
    float* sYt = sm + OFF_YT;
    float* sK  = sm + OFF_K;

    for (int iv = 0; iv < TT - 1; ++iv) {
        float t0v = sm[OFF_TS + iv];
        float h   = 0.5f * (sm[OFF_TS + iv + 1] - t0v);
        for (int sub = 0; sub < 2; ++sub) {
            float tc = t0v + sub * h;
            for (int s = 0; s < 6; ++s) {
                const float* aIn = (s == 0) ? sY : sYt;
                vf_eval(sm, tc + h * c_C6[s], aIn, sK + s * 64 * 16, tid);
                if (s < 5) {
                    for (int i = tid; i < MT * DD; i += NTH) {
                        int d = i >> 4, m = i & 15;
                        int off = d * 16 + m;
                        float acc = sY[off];
                        for (int j = 0; j <= s; ++j)
                            acc += h * c_A[(s + 1) * 5 + j] * sK[j * 64 * 16 + off];
                        sYt[off] = acc;
                    }
                    __syncthreads();
                }
            }
            for (int i = tid; i < MT * DD; i += NTH) {
                int d = i >> 4, m = i & 15;
                int off = d * 16 + m;
                float acc = sY[off];
                acc += h * (c_B6[0] * sK[0 * 64 * 16 + off]
                          + c_B6[2] * sK[2 * 64 * 16 + off]
                          + c_B6[3] * sK[3 * 64 * 16 + off]
                          + c_B6[4] * sK[4 * 64 * 16 + off]
                          + c_B6[5] * sK[5 * 64 * 16 + off]);
                sY[off] = acc;
            }
            __syncthreads();
        }
        float* dst = out + (size_t)(iv + 1) * BB * DD + (size_t)r0 * DD;
        for (int i = tid; i < MT * DD; i += NTH) {
            int m = i >> 6, d = i & 63;
            dst[i] = sY[d * 16 + m];
        }
    }
}

extern "C" void kernel_launch(void* const* d_in, const int* in_sizes, int n_in,
                              void* d_out, int out_size) {
    if (n_in < 8) return;
    const float* ts = (const float*)d_in[0];
    const float* y0 = (const float*)d_in[1];
    const float* W0 = (const float*)d_in[2];
    const float* b0 = (const float*)d_in[3];
    const float* W1 = (const float*)d_in[4];
    const float* b1 = (const float*)d_in[5];
    const float* W2 = (const float*)d_in[6];
    const float* b2 = (const float*)d_in[7];
    float* out = (float*)d_out;

    cudaFuncSetAttribute(ode_kernel, cudaFuncAttributeMaxDynamicSharedMemorySize, SMEM_BYTES);

    prep_kernel<<<256, NTH>>>(W1, y0, out);
    ode_kernel<<<NCTA, NTH, SMEM_BYTES>>>(ts, y0, W0, b0, b1, W2, b2, out);
}

// round 7
// speedup vs baseline: 1.0807x; 1.0807x over previous
#include <cuda_runtime.h>

typedef unsigned long long ull;
#define DEVFN __device__ __forceinline__

#define TT 32
#define BB 2048
#define DD 64
#define MT 16
#define NTH 512
#define NCTA (BB / MT)
#define PITCH 20

// smem layout (float offsets)
#define OFF_W0T 0                       // [64][256]  W0T[d][w] = W0[w][d]
#define OFF_W2T (OFF_W0T + 64*256)      // [256][64]  W2T[u][d] = W2[d][u]
#define OFF_B0  (OFF_W2T + 256*64)
#define OFF_B1  (OFF_B0 + 256)
#define OFF_B2  (OFF_B1 + 256)
#define OFF_TS  (OFF_B2 + 64)
#define OFF_Y   (OFF_TS + 32)           // [64][PITCH]
#define OFF_YT  (OFF_Y + 64*PITCH)
#define OFF_K   (OFF_YT + 64*PITCH)     // 6 x [64][PITCH]
#define OFF_H0  (OFF_K + 6*64*PITCH)    // [256][PITCH]
#define OFF_H1  (OFF_H0 + 256*PITCH)
#define SMEM_FLOATS (OFF_H1 + 256*PITCH)
#define SMEM_BYTES (SMEM_FLOATS * 4)    // 215424

__device__ float g_W1T[(256 + 16) * 256];   // [k][w]

__constant__ float c_A[30] = {
    0.f, 0.f, 0.f, 0.f, 0.f,
    0.2f, 0.f, 0.f, 0.f, 0.f,
    (float)(3.0/40.0), (float)(9.0/40.0), 0.f, 0.f, 0.f,
    (float)(44.0/45.0), (float)(-56.0/15.0), (float)(32.0/9.0), 0.f, 0.f,
    (float)(19372.0/6561.0), (float)(-25360.0/2187.0), (float)(64448.0/6561.0), (float)(-212.0/729.0), 0.f,
    (float)(9017.0/3168.0), (float)(-355.0/33.0), (float)(46732.0/5247.0), (float)(49.0/176.0), (float)(-5103.0/18656.0)
};
__constant__ float c_C6[6] = {0.f, 0.2f, 0.3f, 0.8f, (float)(8.0/9.0), 1.f};
__constant__ float c_B6[6] = {(float)(35.0/384.0), 0.f, (float)(500.0/1113.0),
                              (float)(125.0/192.0), (float)(-2187.0/6784.0), (float)(11.0/84.0)};

DEVFN ull dup2(float x) {
    ull r; unsigned xi = __float_as_uint(x);
    asm("mov.b64 %0, {%1, %1};" : "=l"(r) : "r"(xi));
    return r;
}
DEVFN void fma2(ull& d, ull a, ull b) {
    asm("fma.rn.f32x2 %0, %1, %2, %0;" : "+l"(d) : "l"(a), "l"(b));
}
DEVFN void unpk(ull v, float& lo, float& hi) {
    unsigned a, b;
    asm("mov.b64 {%0, %1}, %2;" : "=r"(a), "=r"(b) : "l"(v));
    lo = __uint_as_float(a); hi = __uint_as_float(b);
}
DEVFN float fast_tanh(float x) {
    float ax = fabsf(x);
    float e  = __expf(-2.0f * ax);
    float r  = __fdividef(1.0f - e, 1.0f + e);
    return copysignf(r, x);
}

// acc[p] = row-pair (8rh+2p, 8rh+2p+1) of one output column; A row-pairs plain, B dup'd
DEVFN void gstep4(ull (&acc)[4], float bval, const float* pa) {
    ull bb = dup2(bval);
    ulonglong2 a0 = *reinterpret_cast<const ulonglong2*>(pa);
    ulonglong2 a1 = *reinterpret_cast<const ulonglong2*>(pa + 4);
    fma2(acc[0], a0.x, bb); fma2(acc[1], a0.y, bb);
    fma2(acc[2], a1.x, bb); fma2(acc[3], a1.y, bb);
}

// kout = (tanh(tanh(aIn@W0T + b0)@W1T + b1)@W2T + b2) * exp(tstage)
DEVFN void vf_eval(float* sm, float tstage, const float* aIn, float* kout, int tid) {
    float et = expf(tstage);
    int w  = tid & 255;      // output column for GEMM0/GEMM1
    int rh = tid >> 8;       // row half: rows 8rh .. 8rh+7

    // ---- GEMM0: [16,64] x W0T -> tanh -> h0 ----
    {
        ull acc[4];
#pragma unroll
        for (int p = 0; p < 4; ++p) acc[p] = 0ull;
        const float* pb = sm + OFF_W0T + w;
        const float* pa = aIn + 8 * rh;
#pragma unroll 4
        for (int k = 0; k < 64; ++k)
            gstep4(acc, pb[k * 256], pa + k * PITCH);
        float bj = sm[OFF_B0 + w];
        float v[8];
#pragma unroll
        for (int p = 0; p < 4; ++p) unpk(acc[p], v[2 * p], v[2 * p + 1]);
#pragma unroll
        for (int i = 0; i < 8; ++i) v[i] = fast_tanh(v[i] + bj);
        float* hp = sm + OFF_H0 + w * PITCH + 8 * rh;
        *reinterpret_cast<float4*>(hp)     = make_float4(v[0], v[1], v[2], v[3]);
        *reinterpret_cast<float4*>(hp + 4) = make_float4(v[4], v[5], v[6], v[7]);
    }
    __syncthreads();

    // ---- GEMM1: [16,256] x W1T (L2-streamed, double-buffered) -> tanh -> h1 ----
    {
        ull acc[4];
#pragma unroll
        for (int p = 0; p < 4; ++p) acc[p] = 0ull;
        const float* pb = g_W1T + w;
        const float* pa = sm + OFF_H0 + 8 * rh;
        float bufA[8], bufB[8];
#pragma unroll
        for (int kk = 0; kk < 8; ++kk) bufA[kk] = pb[kk * 256];
        pb += 8 * 256;
#pragma unroll 1
        for (int kc = 0; kc < 256; kc += 16) {
#pragma unroll
            for (int kk = 0; kk < 8; ++kk) bufB[kk] = pb[kk * 256];
            pb += 8 * 256;
#pragma unroll
            for (int kk = 0; kk < 8; ++kk)
                gstep4(acc, bufA[kk], pa + (kc + kk) * PITCH);
#pragma unroll
            for (int kk = 0; kk < 8; ++kk) bufA[kk] = pb[kk * 256];
            pb += 8 * 256;
#pragma unroll
            for (int kk = 0; kk < 8; ++kk)
                gstep4(acc, bufB[kk], pa + (kc + 8 + kk) * PITCH);
        }
        float bj = sm[OFF_B1 + w];
        float v[8];
#pragma unroll
        for (int p = 0; p < 4; ++p) unpk(acc[p], v[2 * p], v[2 * p + 1]);
#pragma unroll
        for (int i = 0; i < 8; ++i) v[i] = fast_tanh(v[i] + bj);
        float* hp = sm + OFF_H1 + w * PITCH + 8 * rh;
        *reinterpret_cast<float4*>(hp)     = make_float4(v[0], v[1], v[2], v[3]);
        *reinterpret_cast<float4*>(hp + 4) = make_float4(v[4], v[5], v[6], v[7]);
    }
    __syncthreads();

    // ---- GEMM2: [16,256] x W2T (smem) -> kout ----
    {
        int d = tid & 63, q = tid >> 6;          // col d, rows 2q, 2q+1 (q = 0..7)
        ull acc2 = 0ull;
        const float* pb = sm + OFF_W2T + d;
        const float* pa = sm + OFF_H1 + 2 * q;
#pragma unroll 8
        for (int u = 0; u < 256; ++u) {
            ull bb = dup2(pb[u * 64]);
            ull av = *reinterpret_cast<const ull*>(pa + u * PITCH);
            fma2(acc2, av, bb);
        }
        float bd = sm[OFF_B2 + d];
        float v0, v1; unpk(acc2, v0, v1);
        kout[d * PITCH + 2 * q]     = (v0 + bd) * et;
        kout[d * PITCH + 2 * q + 1] = (v1 + bd) * et;
    }
    __syncthreads();
}

__global__ void __launch_bounds__(256, 1)
prep_kernel(const float* __restrict__ W1, const float* __restrict__ y0,
            float* __restrict__ out) {
    int stride = gridDim.x * blockDim.x;
    int t0 = blockIdx.x * blockDim.x + threadIdx.x;
    for (int idx = t0; idx < 256 * 256; idx += stride) {
        int r = idx >> 8, c = idx & 255;
        g_W1T[c * 256 + r] = W1[idx];          // g_W1T[k][w] = W1[w][k]
    }
    for (int idx = t0; idx < 16 * 256; idx += stride)
        g_W1T[65536 + idx] = 0.f;              // prefetch-overrun pad
    for (int idx = t0; idx < BB * DD; idx += stride)
        out[idx] = y0[idx];                    // out slice 0 = y0
}

__global__ void __launch_bounds__(NTH, 1)
ode_kernel(const float* __restrict__ ts, const float* __restrict__ y0,
           const float* __restrict__ W0, const float* __restrict__ b0,
           const float* __restrict__ b1,
           const float* __restrict__ W2, const float* __restrict__ b2,
           float* __restrict__ out) {
    extern __shared__ float sm[];
    int tid = threadIdx.x;
    int r0 = blockIdx.x * MT;

    for (int idx = tid; idx < 64 * 256; idx += NTH) {
        int w = idx >> 6, d = idx & 63;
        sm[OFF_W0T + d * 256 + w] = W0[idx];   // W0T[d][w]
    }
    for (int idx = tid; idx < 64 * 256; idx += NTH) {
        int d = idx >> 8, u = idx & 255;
        sm[OFF_W2T + u * 64 + d] = W2[idx];    // W2T[u][d]
    }
    if (tid < 256) { sm[OFF_B0 + tid] = b0[tid]; sm[OFF_B1 + tid] = b1[tid]; }
    if (tid < 64)  sm[OFF_B2 + tid] = b2[tid];
    if (tid < 32)  sm[OFF_TS + tid] = ts[tid];
    for (int i = tid; i < MT * DD; i += NTH) {
        int d = i >> 4, m = i & 15;
        sm[OFF_Y + d * PITCH + m] = y0[(r0 + m) * DD + d];
    }
    __syncthreads();

    float* sY  = sm + OFF_Y;
    float* sYt = sm + OFF_YT;
    float* sK  = sm + OFF_K;

    for (int iv = 0; iv < TT - 1; ++iv) {
        float t0v = sm[OFF_TS + iv];
        float h   = 0.5f * (sm[OFF_TS + iv + 1] - t0v);
        for (int sub = 0; sub < 2; ++sub) {
            float tc = t0v + sub * h;
            for (int s = 0; s < 6; ++s) {
                const float* aIn = (s == 0) ? sY : sYt;
                vf_eval(sm, tc + h * c_C6[s], aIn, sK + s * 64 * PITCH, tid);
                if (s < 5) {
                    for (int i = tid; i < MT * DD; i += NTH) {
                        int d = i >> 4, m = i & 15;
                        int off = d * PITCH + m;
                        float acc = sY[off];
                        for (int j = 0; j <= s; ++j)
                            acc += h * c_A[(s + 1) * 5 + j] * sK[j * 64 * PITCH + off];
                        sYt[off] = acc;
                    }
                    __syncthreads();
                }
            }
            for (int i = tid; i < MT * DD; i += NTH) {
                int d = i >> 4, m = i & 15;
                int off = d * PITCH + m;
                float acc = sY[off];
                acc += h * (c_B6[0] * sK[0 * 64 * PITCH + off]
                          + c_B6[2] * sK[2 * 64 * PITCH + off]
                          + c_B6[3] * sK[3 * 64 * PITCH + off]
                          + c_B6[4] * sK[4 * 64 * PITCH + off]
                          + c_B6[5] * sK[5 * 64 * PITCH + off]);
                sY[off] = acc;
            }
            __syncthreads();
        }
        float* dst = out + (size_t)(iv + 1) * BB * DD + (size_t)r0 * DD;
        for (int i = tid; i < MT * DD; i += NTH) {
            int m = i >> 6, d = i & 63;
            dst[i] = sY[d * PITCH + m];
        }
    }
}

extern "C" void kernel_launch(void* const* d_in, const int* in_sizes, int n_in,
                              void* d_out, int out_size) {
    if (n_in < 8) return;
    const float* ts = (const float*)d_in[0];
    const float* y0 = (const float*)d_in[1];
    const float* W0 = (const float*)d_in[2];
    const float* b0 = (const float*)d_in[3];
    const float* W1 = (const float*)d_in[4];
    const float* b1 = (const float*)d_in[5];
    const float* W2 = (const float*)d_in[6];
    const float* b2 = (const float*)d_in[7];
    float* out = (float*)d_out;

    cudaFuncSetAttribute(ode_kernel, cudaFuncAttributeMaxDynamicSharedMemorySize, SMEM_BYTES);

    prep_kernel<<<256, 256>>>(W1, y0, out);
    ode_kernel<<<NCTA, NTH, SMEM_BYTES>>>(ts, y0, W0, b0, b1, W2, b2, out);
}

// round 9
// speedup vs baseline: 1.4779x; 1.3676x over previous
#include <cuda_runtime.h>

typedef unsigned long long ull;
#define DEVFN __device__ __forceinline__

#define TT 32
#define BB 2048
#define DD 64
#define MT 16
#define NTH 256
#define NCTA (BB / MT)
#define PITCH 20

// smem layout (float offsets)
#define OFF_W0T 0                       // [64][256]  W0T[d][w] = W0[w][d]
#define OFF_W2T (OFF_W0T + 64*256)      // [256][64]  W2T[u][d] = W2[d][u]
#define OFF_B0  (OFF_W2T + 256*64)
#define OFF_B1  (OFF_B0 + 256)
#define OFF_B2  (OFF_B1 + 256)
#define OFF_TS  (OFF_B2 + 64)
#define OFF_Y   (OFF_TS + 32)           // [64][PITCH]
#define OFF_YT  (OFF_Y + 64*PITCH)
#define OFF_K   (OFF_YT + 64*PITCH)     // 6 x [64][PITCH]
#define OFF_H0  (OFF_K + 6*64*PITCH)    // [256][PITCH]
#define OFF_H1  (OFF_H0 + 256*PITCH)    // [256][PITCH]
#define OFF_SCR (OFF_H1 + 256*PITCH)    // 4096 floats reduction scratch
#define SMEM_FLOATS (OFF_SCR + 4096)    // 57952
#define SMEM_BYTES (SMEM_FLOATS * 4)    // 231808 (<= 232448)

__device__ float g_W1T[(256 + 16) * 256];   // [k][w], w contiguous

__constant__ float c_A[30] = {
    0.f, 0.f, 0.f, 0.f, 0.f,
    0.2f, 0.f, 0.f, 0.f, 0.f,
    (float)(3.0/40.0), (float)(9.0/40.0), 0.f, 0.f, 0.f,
    (float)(44.0/45.0), (float)(-56.0/15.0), (float)(32.0/9.0), 0.f, 0.f,
    (float)(19372.0/6561.0), (float)(-25360.0/2187.0), (float)(64448.0/6561.0), (float)(-212.0/729.0), 0.f,
    (float)(9017.0/3168.0), (float)(-355.0/33.0), (float)(46732.0/5247.0), (float)(49.0/176.0), (float)(-5103.0/18656.0)
};
__constant__ float c_C6[6] = {0.f, 0.2f, 0.3f, 0.8f, (float)(8.0/9.0), 1.f};
__constant__ float c_B6[6] = {(float)(35.0/384.0), 0.f, (float)(500.0/1113.0),
                              (float)(125.0/192.0), (float)(-2187.0/6784.0), (float)(11.0/84.0)};

DEVFN ull dup2(float x) {
    ull r; unsigned xi = __float_as_uint(x);
    asm("mov.b64 %0, {%1, %1};" : "=l"(r) : "r"(xi));
    return r;
}
DEVFN void fma2(ull& d, ull a, ull b) {
    asm("fma.rn.f32x2 %0, %1, %2, %0;" : "+l"(d) : "l"(a), "l"(b));
}
DEVFN void unpk(ull v, float& lo, float& hi) {
    unsigned a, b;
    asm("mov.b64 {%0, %1}, %2;" : "=r"(a), "=r"(b) : "l"(v));
    lo = __uint_as_float(a); hi = __uint_as_float(b);
}
DEVFN float fast_tanh(float x) {
    float ax = fabsf(x);
    float e  = __expf(-2.0f * ax);
    float r  = __fdividef(1.0f - e, 1.0f + e);
    return copysignf(r, x);
}

// 4 fma2 on one column (acc[0..3] = row-pairs 0..3) with dup'd B
DEVFN void col4(ull* acc, ull bb, const ulonglong2& a01, const ulonglong2& a23) {
    fma2(acc[0], a01.x, bb); fma2(acc[1], a01.y, bb);
    fma2(acc[2], a23.x, bb); fma2(acc[3], a23.y, bb);
}

// kout = (tanh(tanh(aIn@W0T + b0)@W1T + b1)@W2T + b2) * exp(tstage)
DEVFN void vf_eval(float* sm, float tstage, const float* aIn, float* kout, int tid) {
    float et = expf(tstage);
    float* scr = sm + OFF_SCR;

    // ---- GEMM0: col-pair (cp) x row-half (rh), no split ----
    {
        int cp = tid & 127, rh = tid >> 7;
        int c0 = 2 * cp, rb = 8 * rh;
        ull acc[2][4];
#pragma unroll
        for (int i = 0; i < 2; ++i)
#pragma unroll
            for (int p = 0; p < 4; ++p) acc[i][p] = 0ull;
        const float* pa = aIn + rb;
        const float* pb = sm + OFF_W0T + c0;
#pragma unroll 4
        for (int k = 0; k < 64; ++k) {
            float2 b2 = *reinterpret_cast<const float2*>(pb + k * 256);
            ulonglong2 a01 = *reinterpret_cast<const ulonglong2*>(pa + k * PITCH);
            ulonglong2 a23 = *reinterpret_cast<const ulonglong2*>(pa + k * PITCH + 4);
            col4(acc[0], dup2(b2.x), a01, a23);
            col4(acc[1], dup2(b2.y), a01, a23);
        }
#pragma unroll
        for (int ci = 0; ci < 2; ++ci) {
            float bj = sm[OFF_B0 + c0 + ci];
            float v[8];
#pragma unroll
            for (int p = 0; p < 4; ++p) unpk(acc[ci][p], v[2 * p], v[2 * p + 1]);
#pragma unroll
            for (int i = 0; i < 8; ++i) v[i] = fast_tanh(v[i] + bj);
            float* hp = sm + OFF_H0 + (c0 + ci) * PITCH + rb;
            *reinterpret_cast<float4*>(hp)     = make_float4(v[0], v[1], v[2], v[3]);
            *reinterpret_cast<float4*>(hp + 4) = make_float4(v[4], v[5], v[6], v[7]);
        }
    }
    __syncthreads();

    // ---- GEMM1: col-quad (cg) x row-half (rh) x k-parity (kh); B via LDG.128 ----
    {
        int kh = tid >> 7, tile = tid & 127;
        int cg = tile >> 1, rh = tile & 1;
        int c0 = 4 * cg, rb = 8 * rh;
        ull acc[4][4];
#pragma unroll
        for (int i = 0; i < 4; ++i)
#pragma unroll
            for (int p = 0; p < 4; ++p) acc[i][p] = 0ull;
        const float* pa = sm + OFF_H0 + rb;
        const float* pb = g_W1T + kh * 256 + c0;   // k = 2j + kh -> +j*512
        float4 bbuf[4];
#pragma unroll
        for (int jj = 0; jj < 4; ++jj)
            bbuf[jj] = *reinterpret_cast<const float4*>(pb + jj * 512);
#pragma unroll 4
        for (int j = 0; j < 128; ++j) {
            float4 b4 = bbuf[j & 3];
            bbuf[j & 3] = *reinterpret_cast<const float4*>(pb + (j + 4) * 512);
            int k = 2 * j + kh;
            ulonglong2 a01 = *reinterpret_cast<const ulonglong2*>(pa + k * PITCH);
            ulonglong2 a23 = *reinterpret_cast<const ulonglong2*>(pa + k * PITCH + 4);
            col4(acc[0], dup2(b4.x), a01, a23);
            col4(acc[1], dup2(b4.y), a01, a23);
            col4(acc[2], dup2(b4.z), a01, a23);
            col4(acc[3], dup2(b4.w), a01, a23);
        }
        // reduce the two k-parities via scratch
        float* st = scr + tile * 32;
        if (kh) {
#pragma unroll
            for (int ci = 0; ci < 4; ++ci) {
                ulonglong2 w0, w1;
                w0.x = acc[ci][0]; w0.y = acc[ci][1];
                w1.x = acc[ci][2]; w1.y = acc[ci][3];
                *reinterpret_cast<ulonglong2*>(st + ci * 8)     = w0;
                *reinterpret_cast<ulonglong2*>(st + ci * 8 + 4) = w1;
            }
        }
        __syncthreads();
        if (!kh) {
#pragma unroll
            for (int ci = 0; ci < 4; ++ci) {
                float bj = sm[OFF_B1 + c0 + ci];
                ulonglong2 q0 = *reinterpret_cast<const ulonglong2*>(st + ci * 8);
                ulonglong2 q1 = *reinterpret_cast<const ulonglong2*>(st + ci * 8 + 4);
                float v[8], u[8];
                unpk(acc[ci][0], v[0], v[1]); unpk(acc[ci][1], v[2], v[3]);
                unpk(acc[ci][2], v[4], v[5]); unpk(acc[ci][3], v[6], v[7]);
                unpk(q0.x, u[0], u[1]); unpk(q0.y, u[2], u[3]);
                unpk(q1.x, u[4], u[5]); unpk(q1.y, u[6], u[7]);
#pragma unroll
                for (int i = 0; i < 8; ++i) v[i] = fast_tanh(v[i] + u[i] + bj);
                float* hp = sm + OFF_H1 + (c0 + ci) * PITCH + rb;
                *reinterpret_cast<float4*>(hp)     = make_float4(v[0], v[1], v[2], v[3]);
                *reinterpret_cast<float4*>(hp + 4) = make_float4(v[4], v[5], v[6], v[7]);
            }
        }
    }
    __syncthreads();

    // ---- GEMM2: col-pair (cp) x row-half (rh) x u-split-4 (us) ----
    {
        int us = tid >> 6, t2 = tid & 63;
        int rh = t2 >> 5, cp = t2 & 31;
        int d0 = 2 * cp, rb = 8 * rh;
        ull acc[2][4];
#pragma unroll
        for (int i = 0; i < 2; ++i)
#pragma unroll
            for (int p = 0; p < 4; ++p) acc[i][p] = 0ull;
        const float* pa = sm + OFF_H1 + rb;
        const float* pb = sm + OFF_W2T + d0;
        int u0 = us * 64;
#pragma unroll 4
        for (int j = 0; j < 64; ++j) {
            int u = u0 + j;
            float2 b2 = *reinterpret_cast<const float2*>(pb + u * 64);
            ulonglong2 a01 = *reinterpret_cast<const ulonglong2*>(pa + u * PITCH);
            ulonglong2 a23 = *reinterpret_cast<const ulonglong2*>(pa + u * PITCH + 4);
            col4(acc[0], dup2(b2.x), a01, a23);
            col4(acc[1], dup2(b2.y), a01, a23);
        }
        if (us) {
            float* st = scr + ((us - 1) * 64 + t2) * 16;
#pragma unroll
            for (int ci = 0; ci < 2; ++ci) {
                ulonglong2 w0, w1;
                w0.x = acc[ci][0]; w0.y = acc[ci][1];
                w1.x = acc[ci][2]; w1.y = acc[ci][3];
                *reinterpret_cast<ulonglong2*>(st + ci * 8)     = w0;
                *reinterpret_cast<ulonglong2*>(st + ci * 8 + 4) = w1;
            }
        }
        __syncthreads();
        if (us == 0) {
#pragma unroll
            for (int ci = 0; ci < 2; ++ci) {
                float v[8];
                unpk(acc[ci][0], v[0], v[1]); unpk(acc[ci][1], v[2], v[3]);
                unpk(acc[ci][2], v[4], v[5]); unpk(acc[ci][3], v[6], v[7]);
#pragma unroll
                for (int p = 0; p < 3; ++p) {
                    const float* st = scr + (p * 64 + t2) * 16;
                    ulonglong2 q0 = *reinterpret_cast<const ulonglong2*>(st + ci * 8);
                    ulonglong2 q1 = *reinterpret_cast<const ulonglong2*>(st + ci * 8 + 4);
                    float u[8];
                    unpk(q0.x, u[0], u[1]); unpk(q0.y, u[2], u[3]);
                    unpk(q1.x, u[4], u[5]); unpk(q1.y, u[6], u[7]);
#pragma unroll
                    for (int i = 0; i < 8; ++i) v[i] += u[i];
                }
                float bd = sm[OFF_B2 + d0 + ci];
                float* kd = kout + (d0 + ci) * PITCH + rb;
#pragma unroll
                for (int i = 0; i < 8; ++i) v[i] = (v[i] + bd) * et;
                *reinterpret_cast<float4*>(kd)     = make_float4(v[0], v[1], v[2], v[3]);
                *reinterpret_cast<float4*>(kd + 4) = make_float4(v[4], v[5], v[6], v[7]);
            }
        }
    }
    __syncthreads();
}

__global__ void __launch_bounds__(256, 1)
prep_kernel(const float* __restrict__ W1, const float* __restrict__ y0,
            float* __restrict__ out) {
    int stride = gridDim.x * blockDim.x;
    int t0 = blockIdx.x * blockDim.x + threadIdx.x;
    for (int idx = t0; idx < 256 * 256; idx += stride) {
        int r = idx >> 8, c = idx & 255;
        g_W1T[c * 256 + r] = W1[idx];          // g_W1T[k][w] = W1[w][k]
    }
    for (int idx = t0; idx < 16 * 256; idx += stride)
        g_W1T[65536 + idx] = 0.f;              // prefetch-overrun pad
    for (int idx = t0; idx < BB * DD; idx += stride)
        out[idx] = y0[idx];                    // out slice 0 = y0
}

__global__ void __launch_bounds__(NTH, 1)
ode_kernel(const float* __restrict__ ts, const float* __restrict__ y0,
           const float* __restrict__ W0, const float* __restrict__ b0,
           const float* __restrict__ b1,
           const float* __restrict__ W2, const float* __restrict__ b2,
           float* __restrict__ out) {
    extern __shared__ float sm[];
    int tid = threadIdx.x;
    int r0 = blockIdx.x * MT;

    for (int idx = tid; idx < 64 * 256; idx += NTH) {
        int w = idx >> 6, d = idx & 63;
        sm[OFF_W0T + d * 256 + w] = W0[idx];   // W0T[d][w]
    }
    for (int idx = tid; idx < 64 * 256; idx += NTH) {
        int d = idx >> 8, u = idx & 255;
        sm[OFF_W2T + u * 64 + d] = W2[idx];    // W2T[u][d]
    }
    if (tid < 256) { sm[OFF_B0 + tid] = b0[tid]; sm[OFF_B1 + tid] = b1[tid]; }
    if (tid < 64)  sm[OFF_B2 + tid] = b2[tid];
    if (tid < 32)  sm[OFF_TS + tid] = ts[tid];
    for (int i = tid; i < MT * DD; i += NTH) {
        int d = i >> 4, m = i & 15;
        sm[OFF_Y + d * PITCH + m] = y0[(r0 + m) * DD + d];
    }
    __syncthreads();

    float* sY  = sm + OFF_Y;
    float* sYt = sm + OFF_YT;
    float* sK  = sm + OFF_K;

    for (int iv = 0; iv < TT - 1; ++iv) {
        float t0v = sm[OFF_TS + iv];
        float h   = 0.5f * (sm[OFF_TS + iv + 1] - t0v);
        for (int sub = 0; sub < 2; ++sub) {
            float tc = t0v + sub * h;
            for (int s = 0; s < 6; ++s) {
                const float* aIn = (s == 0) ? sY : sYt;
                vf_eval(sm, tc + h * c_C6[s], aIn, sK + s * 64 * PITCH, tid);
                if (s < 5) {
                    for (int i = tid; i < MT * DD; i += NTH) {
                        int d = i >> 4, m = i & 15;
                        int off = d * PITCH + m;
                        float acc = sY[off];
                        for (int j = 0; j <= s; ++j)
                            acc += h * c_A[(s + 1) * 5 + j] * sK[j * 64 * PITCH + off];
                        sYt[off] = acc;
                    }
                    __syncthreads();
                }
            }
            for (int i = tid; i < MT * DD; i += NTH) {
                int d = i >> 4, m = i & 15;
                int off = d * PITCH + m;
                float acc = sY[off];
                acc += h * (c_B6[0] * sK[0 * 64 * PITCH + off]
                          + c_B6[2] * sK[2 * 64 * PITCH + off]
                          + c_B6[3] * sK[3 * 64 * PITCH + off]
                          + c_B6[4] * sK[4 * 64 * PITCH + off]
                          + c_B6[5] * sK[5 * 64 * PITCH + off]);
                sY[off] = acc;
            }
            __syncthreads();
        }
        float* dst = out + (size_t)(iv + 1) * BB * DD + (size_t)r0 * DD;
        for (int i = tid; i < MT * DD; i += NTH) {
            int m = i >> 6, d = i & 63;
            dst[i] = sY[d * PITCH + m];
        }
    }
}

extern "C" void kernel_launch(void* const* d_in, const int* in_sizes, int n_in,
                              void* d_out, int out_size) {
    if (n_in < 8) return;
    const float* ts = (const float*)d_in[0];
    const float* y0 = (const float*)d_in[1];
    const float* W0 = (const float*)d_in[2];
    const float* b0 = (const float*)d_in[3];
    const float* W1 = (const float*)d_in[4];
    const float* b1 = (const float*)d_in[5];
    const float* W2 = (const float*)d_in[6];
    const float* b2 = (const float*)d_in[7];
    float* out = (float*)d_out;

    cudaFuncSetAttribute(ode_kernel, cudaFuncAttributeMaxDynamicSharedMemorySize, SMEM_BYTES);

    prep_kernel<<<256, 256>>>(W1, y0, out);
    ode_kernel<<<NCTA, NTH, SMEM_BYTES>>>(ts, y0, W0, b0, b1, W2, b2, out);
}